// round 1
// baseline (speedup 1.0000x reference)
#include <cuda_runtime.h>
#include <cuda_bf16.h>
#include <math.h>

// skipgram loss: one warp per batch element.
// Inputs (metadata order): u_weight[V*D] f32, v_weight[V*D] f32,
// u_pos[B] i32, v_pos[B] i32, v_neg[B*N] i32, batch_size (scalar).
// D=128, N=10 fixed for this problem instance. B from in_sizes[2].

#define D 128
#define NNEG 10
#define WARPS_PER_BLOCK 8
#define BLOCK_THREADS (WARPS_PER_BLOCK * 32)

__device__ __forceinline__ float log_sigmoid_f(float x) {
    // log(sigmoid(x)) = min(x,0) - log1p(exp(-|x|)), numerically stable
    return fminf(x, 0.0f) - log1pf(expf(-fabsf(x)));
}

__global__ void skipgram_kernel(const float* __restrict__ u_w,
                                const float* __restrict__ v_w,
                                const int* __restrict__ u_pos,
                                const int* __restrict__ v_pos,
                                const int* __restrict__ v_neg,
                                float* __restrict__ out,
                                int B, float neg_inv_B) {
    const int gwarp = (blockIdx.x * BLOCK_THREADS + threadIdx.x) >> 5;
    const int lane  = threadIdx.x & 31;
    const int wid   = threadIdx.x >> 5;

    float val = 0.0f;
    if (gwarp < B) {
        const size_t ui = (size_t)u_pos[gwarp];
        const size_t vi = (size_t)v_pos[gwarp];

        // Each lane holds 4 contiguous floats of the 128-float row (float4).
        const float4 u4 = reinterpret_cast<const float4*>(u_w + ui * D)[lane];
        const float4 v4 = reinterpret_cast<const float4*>(v_w + vi * D)[lane];

        float pdot = u4.x * v4.x + u4.y * v4.y + u4.z * v4.z + u4.w * v4.w;

        float nacc = 0.0f;
        const int* nbase = v_neg + (size_t)gwarp * NNEG;
        #pragma unroll
        for (int n = 0; n < NNEG; n++) {
            const size_t ni = (size_t)nbase[n];
            const float4 w4 = reinterpret_cast<const float4*>(v_w + ni * D)[lane];
            nacc += u4.x * w4.x + u4.y * w4.y + u4.z * w4.z + u4.w * w4.w;
        }

        // One butterfly reduction pass for both accumulators.
        #pragma unroll
        for (int off = 16; off > 0; off >>= 1) {
            pdot += __shfl_xor_sync(0xffffffffu, pdot, off);
            nacc += __shfl_xor_sync(0xffffffffu, nacc, off);
        }

        const float score  = pdot * (1.0f / (float)D);  // mean over D
        const float nscore = nacc * (1.0f / (float)NNEG); // mean over N (dots are sums over D)

        const float lt = log_sigmoid_f(score);
        const float ls = log_sigmoid_f(-nscore);
        val = (lt + ls) * neg_inv_B;  // fold -1/B here
    }

    // Block reduction: lane 0 of each warp -> smem -> warp 0 -> one atomicAdd.
    __shared__ float sm[WARPS_PER_BLOCK];
    if (lane == 0) sm[wid] = val;
    __syncthreads();
    if (threadIdx.x < WARPS_PER_BLOCK) {
        float v = sm[threadIdx.x];
        #pragma unroll
        for (int off = WARPS_PER_BLOCK / 2; off > 0; off >>= 1)
            v += __shfl_xor_sync(0xffu, v, off);
        if (threadIdx.x == 0) atomicAdd(out, v);
    }
}

extern "C" void kernel_launch(void* const* d_in, const int* in_sizes, int n_in,
                              void* d_out, int out_size) {
    const float* u_w  = (const float*)d_in[0];
    const float* v_w  = (const float*)d_in[1];
    const int* u_pos  = (const int*)d_in[2];
    const int* v_pos  = (const int*)d_in[3];
    const int* v_neg  = (const int*)d_in[4];
    float* out        = (float*)d_out;

    const int B = in_sizes[2];

    cudaMemsetAsync(out, 0, sizeof(float), 0);

    const int total_warps = B;
    const int blocks = (total_warps + WARPS_PER_BLOCK - 1) / WARPS_PER_BLOCK;
    skipgram_kernel<<<blocks, BLOCK_THREADS>>>(u_w, v_w, u_pos, v_pos, v_neg,
                                               out, B, -1.0f / (float)B);
}